// round 5
// baseline (speedup 1.0000x reference)
#include <cuda_runtime.h>
#include <cuda_bf16.h>
#include <cstdint>
#include <cstddef>

#define T_STEPS 8192
#define F_DIM   1024
#define H_DIM   2048
#define G_DIM   (4 * H_DIM)   // 8192 gate rows
#define MAXB    256           // max persistent blocks (partial-array stride)

// ---------------------------------------------------------------------------
// Scratch (static device allocations only — no cudaMalloc anywhere)
// ---------------------------------------------------------------------------
__device__ float          g_XG[(size_t)T_STEPS * G_DIM];   // 256 MB  x-gates
__device__ __nv_bfloat16  g_Whh[(size_t)G_DIM * H_DIM];    // 32 MB   bf16 W_hh
__device__ float          g_h[2][H_DIM];                   // double-buffered h
__device__ float          g_partial[(size_t)T_STEPS * MAXB]; // per-block out partials
__device__ unsigned       g_bar;                           // grid barrier counter

// ---------------------------------------------------------------------------
// Kernel 1: convert W_hh fp32 -> bf16
// ---------------------------------------------------------------------------
__global__ void convert_whh(const float* __restrict__ W) {
    int i = blockIdx.x * blockDim.x + threadIdx.x;     // one float4 per thread
    const int n4 = (G_DIM * H_DIM) / 4;
    if (i >= n4) return;
    float4 v = reinterpret_cast<const float4*>(W)[i];
    __nv_bfloat162* o = reinterpret_cast<__nv_bfloat162*>(g_Whh);
    o[i * 2 + 0] = __floats2bfloat162_rn(v.x, v.y);
    o[i * 2 + 1] = __floats2bfloat162_rn(v.z, v.w);
}

// ---------------------------------------------------------------------------
// Kernel 2: XG[t,g] = sum_f X[t,f] * Wih[g,f]  + b_ih[g] + b_hh[g]
// 128x128 tile, BK=16, 256 threads, 8x8 per-thread microtile, fp32.
// ---------------------------------------------------------------------------
__global__ __launch_bounds__(256, 2) void gemm_xg(
    const float* __restrict__ X,    // [T, F]
    const float* __restrict__ Wih,  // [G, F]
    const float* __restrict__ bi,
    const float* __restrict__ bh)
{
    __shared__ __align__(16) float As[16][128];
    __shared__ __align__(16) float Bs[16][128];

    const int bm = blockIdx.y * 128;   // t
    const int bn = blockIdx.x * 128;   // g
    const int tid = threadIdx.x;
    const int tx = tid & 15, ty = tid >> 4;
    const int lr = tid >> 1, lc = (tid & 1) << 3;

    float acc[8][8];
#pragma unroll
    for (int i = 0; i < 8; i++)
#pragma unroll
        for (int j = 0; j < 8; j++) acc[i][j] = 0.f;

    const float4* Ag = reinterpret_cast<const float4*>(X   + (size_t)(bm + lr) * F_DIM + lc);
    const float4* Bg = reinterpret_cast<const float4*>(Wih + (size_t)(bn + lr) * F_DIM + lc);

    for (int k0 = 0; k0 < F_DIM; k0 += 16) {
        float4 a0 = Ag[0], a1 = Ag[1];
        float4 b0 = Bg[0], b1 = Bg[1];
        Ag += 4; Bg += 4;
        __syncthreads();   // previous tile's compute finished
        As[lc + 0][lr] = a0.x; As[lc + 1][lr] = a0.y; As[lc + 2][lr] = a0.z; As[lc + 3][lr] = a0.w;
        As[lc + 4][lr] = a1.x; As[lc + 5][lr] = a1.y; As[lc + 6][lr] = a1.z; As[lc + 7][lr] = a1.w;
        Bs[lc + 0][lr] = b0.x; Bs[lc + 1][lr] = b0.y; Bs[lc + 2][lr] = b0.z; Bs[lc + 3][lr] = b0.w;
        Bs[lc + 4][lr] = b1.x; Bs[lc + 5][lr] = b1.y; Bs[lc + 6][lr] = b1.z; Bs[lc + 7][lr] = b1.w;
        __syncthreads();
#pragma unroll
        for (int kk = 0; kk < 16; kk++) {
            float4 af0 = *reinterpret_cast<const float4*>(&As[kk][ty * 8]);
            float4 af1 = *reinterpret_cast<const float4*>(&As[kk][ty * 8 + 4]);
            float4 bf0 = *reinterpret_cast<const float4*>(&Bs[kk][tx * 8]);
            float4 bf1 = *reinterpret_cast<const float4*>(&Bs[kk][tx * 8 + 4]);
            float a[8] = {af0.x, af0.y, af0.z, af0.w, af1.x, af1.y, af1.z, af1.w};
            float b[8] = {bf0.x, bf0.y, bf0.z, bf0.w, bf1.x, bf1.y, bf1.z, bf1.w};
#pragma unroll
            for (int i = 0; i < 8; i++)
#pragma unroll
                for (int j = 0; j < 8; j++) acc[i][j] += a[i] * b[j];
        }
    }

    // epilogue: add bias, write 8x8
    float bb[8];
#pragma unroll
    for (int j = 0; j < 8; j++) {
        int g = bn + tx * 8 + j;
        bb[j] = bi[g] + bh[g];
    }
#pragma unroll
    for (int i = 0; i < 8; i++) {
        size_t row = (size_t)(bm + ty * 8 + i) * G_DIM + bn + tx * 8;
        float4 o0 = make_float4(acc[i][0] + bb[0], acc[i][1] + bb[1],
                                acc[i][2] + bb[2], acc[i][3] + bb[3]);
        float4 o1 = make_float4(acc[i][4] + bb[4], acc[i][5] + bb[5],
                                acc[i][6] + bb[6], acc[i][7] + bb[7]);
        reinterpret_cast<float4*>(g_XG + row)[0] = o0;
        reinterpret_cast<float4*>(g_XG + row)[1] = o1;
    }
}

// ---------------------------------------------------------------------------
// Kernel 3: persistent LSTM recurrence.
// One CTA per SM. Each CTA owns J = ~14 hidden units; the 4*J corresponding
// W_hh rows (bf16) live in SMEM for all 8192 steps. c lives in SMEM.
// Per step: matvec slice -> gate activations -> h slice publish -> grid barrier.
// ---------------------------------------------------------------------------
__device__ __forceinline__ float sigf(float x) { return 1.f / (1.f + __expf(-x)); }

__global__ __launch_bounds__(256, 1) void lstm_kernel(
    const float* __restrict__ Wout, int nb)
{
    extern __shared__ unsigned ws[];        // 4*J rows x 1024 u32 (bf16x2) each
    __shared__ float gates_sm[64];          // 4*J <= 56
    __shared__ float c_sm[32];

    const int tid  = threadIdx.x;
    const int lane = tid & 31;
    const int warp = tid >> 5;              // 8 warps
    const int b    = blockIdx.x;

    const int base = (b * H_DIM) / nb;
    const int J    = ((b + 1) * H_DIM) / nb - base;   // 13 or 14

    // --- load this block's W_hh rows into SMEM (4 contiguous chunks) ---
    for (int q = 0; q < 4; q++) {
        const uint4* src = reinterpret_cast<const uint4*>(
            g_Whh + ((size_t)q * H_DIM + base) * H_DIM);
        uint4* dst = reinterpret_cast<uint4*>(ws + q * J * 1024);
        const int cnt = J * 256;            // uint4 per chunk
        for (int i = tid; i < cnt; i += 256) dst[i] = src[i];
    }
    if (tid < J) c_sm[tid] = 0.f;
    const float wout = (warp == 0 && lane < J) ? Wout[base + lane] : 0.f;

    // --- precompute per-warp row metadata (registers, constant-indexed) ---
    int nrows = 0;
    int xgcol[7], wsoff[7], pidx[7];
    for (int p = warp; p < 4 * J; p += 8) {
        int q = p / J, jj = p - q * J;
        xgcol[nrows] = q * H_DIM + base + jj;
        wsoff[nrows] = p * 1024;
        pidx[nrows]  = p;
        nrows++;
    }
    __syncthreads();

    for (int t = 0; t < T_STEPS; t++) {
        const float* hr = g_h[t & 1];
        float*       hw = g_h[(t & 1) ^ 1];

        // preload full h into registers (bypass stale L1: written by other SMs)
        float2 hreg[32];
        const float2* hp = reinterpret_cast<const float2*>(hr);
#pragma unroll
        for (int k = 0; k < 32; k++) hreg[k] = __ldcv(hp + lane + (k << 5));

        const float* xgrow = g_XG + (size_t)t * G_DIM;

#pragma unroll
        for (int r = 0; r < 7; r++) {
            if (r < nrows) {
                float xg = __ldg(xgrow + xgcol[r]);
                const unsigned* wrow = ws + wsoff[r];
                float a0 = 0.f, a1 = 0.f, a2 = 0.f, a3 = 0.f;
#pragma unroll
                for (int k = 0; k < 32; k += 2) {
                    unsigned w0 = wrow[lane + (k << 5)];
                    unsigned w1 = wrow[lane + ((k + 1) << 5)];
                    a0 += __uint_as_float(w0 << 16)          * hreg[k].x;
                    a1 += __uint_as_float(w0 & 0xffff0000u)  * hreg[k].y;
                    a2 += __uint_as_float(w1 << 16)          * hreg[k + 1].x;
                    a3 += __uint_as_float(w1 & 0xffff0000u)  * hreg[k + 1].y;
                }
                float dot = (a0 + a1) + (a2 + a3);
#pragma unroll
                for (int o = 16; o; o >>= 1) dot += __shfl_xor_sync(0xffffffffu, dot, o);
                if (lane == 0) gates_sm[pidx[r]] = dot + xg;
            }
        }
        __syncthreads();

        // --- cell update (warp 0, lanes 0..J-1) + output partial ---
        if (warp == 0) {
            float pv = 0.f;
            if (lane < J) {
                float iv = gates_sm[lane];
                float fv = gates_sm[J + lane];
                float gv = gates_sm[2 * J + lane];
                float ov = gates_sm[3 * J + lane];
                float c  = c_sm[lane];
                float cn = sigf(fv) * c + sigf(iv) * tanhf(gv);
                float hn = sigf(ov) * tanhf(cn);
                c_sm[lane] = cn;
                hw[base + lane] = hn;
                pv = hn * wout;
            }
#pragma unroll
            for (int o = 16; o; o >>= 1) pv += __shfl_xor_sync(0xffffffffu, pv, o);
            if (lane == 0) g_partial[(size_t)t * MAXB + b] = pv;
        }

        // --- grid barrier (monotonic counter, reset by host memset per launch) ---
        __syncthreads();
        if (t < T_STEPS - 1) {
            if (tid == 0) {
                __threadfence();
                atomicAdd(&g_bar, 1u);
                const unsigned target = (unsigned)nb * (unsigned)(t + 1);
                while (atomicAdd(&g_bar, 0u) < target) { }
                __threadfence();
            }
            __syncthreads();
        }
    }
}

// ---------------------------------------------------------------------------
// Kernel 4: out[t] = b_out + sum_b partial[t][b]   (fixed order -> deterministic)
// ---------------------------------------------------------------------------
__global__ void reduce_out(const float* __restrict__ bo, float* __restrict__ out, int nb) {
    int t = blockIdx.x * blockDim.x + threadIdx.x;
    if (t >= T_STEPS) return;
    float s = bo[0];
    const float* p = g_partial + (size_t)t * MAXB;
    for (int b = 0; b < nb; b++) s += p[b];
    out[t] = s;
}

// ---------------------------------------------------------------------------
// Host launcher (graph-capturable: kernels + async memsets only)
// ---------------------------------------------------------------------------
extern "C" void kernel_launch(void* const* d_in, const int* in_sizes, int n_in,
                              void* d_out, int out_size)
{
    const float* input = (const float*)d_in[0];   // [T, 1, F]
    const float* W_ih  = (const float*)d_in[1];   // [4H, F]
    const float* W_hh  = (const float*)d_in[2];   // [4H, H]
    const float* b_ih  = (const float*)d_in[3];
    const float* b_hh  = (const float*)d_in[4];
    const float* W_out = (const float*)d_in[5];   // [1, H]
    const float* b_out = (const float*)d_in[6];
    float* out = (float*)d_out;                   // [T, 1, 1]

    int dev = 0;
    cudaGetDevice(&dev);
    int nsm = 148;
    cudaDeviceGetAttribute(&nsm, cudaDevAttrMultiProcessorCount, dev);
    int nb = nsm;
    if (nb > MAXB) nb = MAXB;
    if (nb > H_DIM) nb = H_DIM;

    const int Jmax = (H_DIM + nb - 1) / nb;                 // 14 @ 152 SMs
    const size_t smem = (size_t)4 * Jmax * 1024 * sizeof(unsigned); // 229376 B

    cudaFuncSetAttribute(lstm_kernel, cudaFuncAttributeMaxDynamicSharedMemorySize, (int)smem);

    void* barp = nullptr; cudaGetSymbolAddress(&barp, g_bar);
    void* hptr = nullptr; cudaGetSymbolAddress(&hptr, g_h);
    cudaMemsetAsync(barp, 0, sizeof(unsigned));
    cudaMemsetAsync(hptr, 0, 2 * H_DIM * sizeof(float));

    convert_whh<<<(G_DIM * H_DIM / 4 + 255) / 256, 256>>>(W_hh);

    dim3 ggrid(G_DIM / 128, T_STEPS / 128);
    gemm_xg<<<ggrid, 256>>>(input, W_ih, b_ih, b_hh);

    lstm_kernel<<<nb, 256, smem>>>(W_out, nb);

    reduce_out<<<(T_STEPS + 255) / 256, 256>>>(b_out, out, nb);
}

// round 6
// speedup vs baseline: 1.5053x; 1.5053x over previous
#include <cuda_runtime.h>
#include <cuda_bf16.h>
#include <cstdint>
#include <cstddef>

#define T_STEPS 8192
#define F_DIM   1024
#define H_DIM   2048
#define G_DIM   (4 * H_DIM)   // 8192 gate rows
#define MAXB    256

// ---------------------------------------------------------------------------
// Static device scratch (no cudaMalloc anywhere)
// ---------------------------------------------------------------------------
__device__ float                         g_XG[(size_t)T_STEPS * G_DIM];   // x-gates, 256 MB
__device__ __nv_bfloat16                 g_Whh[(size_t)G_DIM * H_DIM];    // bf16 W_hh, 32 MB
__device__ __align__(16) __nv_bfloat16   g_hbf[2][H_DIM];                 // double-buffered h (bf16)
__device__ float                         g_partial[(size_t)T_STEPS * MAXB];
__device__ unsigned                      g_bar;

// ---------------------------------------------------------------------------
// Helpers: bf16x2 -> packed f32x2, packed FFMA2, pair sum
// ---------------------------------------------------------------------------
__device__ __forceinline__ uint64_t bf2f32x2(unsigned u) {
    unsigned lo = u << 16;
    unsigned hi = u & 0xffff0000u;
    uint64_t r;
    asm("mov.b64 %0, {%1, %2};" : "=l"(r) : "r"(lo), "r"(hi));
    return r;
}
__device__ __forceinline__ uint64_t fma2(uint64_t a, uint64_t b, uint64_t c) {
    uint64_t d;
    asm("fma.rn.f32x2 %0, %1, %2, %3;" : "=l"(d) : "l"(a), "l"(b), "l"(c));
    return d;
}
__device__ __forceinline__ float f32x2sum(uint64_t a) {
    float x, y;
    asm("mov.b64 {%0, %1}, %2;" : "=f"(x), "=f"(y) : "l"(a));
    return x + y;
}
__device__ __forceinline__ float sigf(float x) { return 1.f / (1.f + __expf(-x)); }

// ---------------------------------------------------------------------------
// Kernel 1: convert W_hh fp32 -> bf16
// ---------------------------------------------------------------------------
__global__ void convert_whh(const float* __restrict__ W) {
    int i = blockIdx.x * blockDim.x + threadIdx.x;     // one float4 per thread
    const int n4 = (G_DIM * H_DIM) / 4;
    if (i >= n4) return;
    float4 v = reinterpret_cast<const float4*>(W)[i];
    __nv_bfloat162* o = reinterpret_cast<__nv_bfloat162*>(g_Whh);
    o[i * 2 + 0] = __floats2bfloat162_rn(v.x, v.y);
    o[i * 2 + 1] = __floats2bfloat162_rn(v.z, v.w);
}

// ---------------------------------------------------------------------------
// Kernel 2: XG[t,g] = X[t,:] . Wih[g,:] + b_ih[g] + b_hh[g]  (fp32 SGEMM)
// ---------------------------------------------------------------------------
__global__ __launch_bounds__(256, 2) void gemm_xg(
    const float* __restrict__ X,    // [T, F]
    const float* __restrict__ Wih,  // [G, F]
    const float* __restrict__ bi,
    const float* __restrict__ bh)
{
    __shared__ __align__(16) float As[16][128];
    __shared__ __align__(16) float Bs[16][128];

    const int bm = blockIdx.y * 128;   // t
    const int bn = blockIdx.x * 128;   // g
    const int tid = threadIdx.x;
    const int tx = tid & 15, ty = tid >> 4;
    const int lr = tid >> 1, lc = (tid & 1) << 3;

    float acc[8][8];
#pragma unroll
    for (int i = 0; i < 8; i++)
#pragma unroll
        for (int j = 0; j < 8; j++) acc[i][j] = 0.f;

    const float4* Ag = reinterpret_cast<const float4*>(X   + (size_t)(bm + lr) * F_DIM + lc);
    const float4* Bg = reinterpret_cast<const float4*>(Wih + (size_t)(bn + lr) * F_DIM + lc);

    for (int k0 = 0; k0 < F_DIM; k0 += 16) {
        float4 a0 = Ag[0], a1 = Ag[1];
        float4 b0 = Bg[0], b1 = Bg[1];
        Ag += 4; Bg += 4;
        __syncthreads();
        As[lc + 0][lr] = a0.x; As[lc + 1][lr] = a0.y; As[lc + 2][lr] = a0.z; As[lc + 3][lr] = a0.w;
        As[lc + 4][lr] = a1.x; As[lc + 5][lr] = a1.y; As[lc + 6][lr] = a1.z; As[lc + 7][lr] = a1.w;
        Bs[lc + 0][lr] = b0.x; Bs[lc + 1][lr] = b0.y; Bs[lc + 2][lr] = b0.z; Bs[lc + 3][lr] = b0.w;
        Bs[lc + 4][lr] = b1.x; Bs[lc + 5][lr] = b1.y; Bs[lc + 6][lr] = b1.z; Bs[lc + 7][lr] = b1.w;
        __syncthreads();
#pragma unroll
        for (int kk = 0; kk < 16; kk++) {
            float4 af0 = *reinterpret_cast<const float4*>(&As[kk][ty * 8]);
            float4 af1 = *reinterpret_cast<const float4*>(&As[kk][ty * 8 + 4]);
            float4 bf0 = *reinterpret_cast<const float4*>(&Bs[kk][tx * 8]);
            float4 bf1 = *reinterpret_cast<const float4*>(&Bs[kk][tx * 8 + 4]);
            float a[8] = {af0.x, af0.y, af0.z, af0.w, af1.x, af1.y, af1.z, af1.w};
            float b[8] = {bf0.x, bf0.y, bf0.z, bf0.w, bf1.x, bf1.y, bf1.z, bf1.w};
#pragma unroll
            for (int i = 0; i < 8; i++)
#pragma unroll
                for (int j = 0; j < 8; j++) acc[i][j] += a[i] * b[j];
        }
    }

    float bb[8];
#pragma unroll
    for (int j = 0; j < 8; j++) {
        int g = bn + tx * 8 + j;
        bb[j] = bi[g] + bh[g];
    }
#pragma unroll
    for (int i = 0; i < 8; i++) {
        size_t row = (size_t)(bm + ty * 8 + i) * G_DIM + bn + tx * 8;
        float4 o0 = make_float4(acc[i][0] + bb[0], acc[i][1] + bb[1],
                                acc[i][2] + bb[2], acc[i][3] + bb[3]);
        float4 o1 = make_float4(acc[i][4] + bb[4], acc[i][5] + bb[5],
                                acc[i][6] + bb[6], acc[i][7] + bb[7]);
        reinterpret_cast<float4*>(g_XG + row)[0] = o0;
        reinterpret_cast<float4*>(g_XG + row)[1] = o1;
    }
}

// ---------------------------------------------------------------------------
// Kernel 3: persistent LSTM recurrence (one CTA per SM, W_hh resident in SMEM)
// ---------------------------------------------------------------------------
__global__ __launch_bounds__(256, 1) void lstm_kernel(
    const float* __restrict__ Wout, int nb)
{
    extern __shared__ uint4 ws4[];          // 4*J weight rows, row-major bf16x2, uint4 view
    __shared__ float gates_sm[64];
    __shared__ float c_sm[16];

    const int tid  = threadIdx.x;
    const int lane = tid & 31;
    const int warp = tid >> 5;              // 8 warps
    const int b    = blockIdx.x;

    const int base = (b * H_DIM) / nb;
    const int J    = ((b + 1) * H_DIM) / nb - base;   // 13 or 14

    // --- stage this block's W_hh rows into SMEM (4 contiguous gate chunks) ---
    for (int q = 0; q < 4; q++) {
        const uint4* src = reinterpret_cast<const uint4*>(
            g_Whh + ((size_t)q * H_DIM + base) * H_DIM);
        uint4* dst = ws4 + q * J * 256;     // 256 uint4 per row (2048 bf16)
        const int cnt = J * 256;
        for (int i = tid; i < cnt; i += 256) dst[i] = src[i];
    }
    if (tid < J) c_sm[tid] = 0.f;
    const float wout = (warp == 0 && lane < J) ? Wout[base + lane] : 0.f;

    // per-warp row metadata
    int nrows = 0;
    int xgcol[7], woff4[7], pidx[7];
    for (int p = warp; p < 4 * J; p += 8) {
        int q = p / J, jj = p - q * J;
        xgcol[nrows] = q * H_DIM + base + jj;
        woff4[nrows] = p * 256;             // uint4 offset of row p
        pidx[nrows]  = p;
        nrows++;
    }
    __syncthreads();

    // prefetch xg for t = 0
    float xgv[7];
#pragma unroll
    for (int r = 0; r < 7; r++) xgv[r] = (r < nrows) ? __ldg(g_XG + xgcol[r]) : 0.f;

    for (int t = 0; t < T_STEPS; t++) {
        // --- load h (bf16, cross-SM -> bypass L1) and expand to packed f32x2 ---
        const uint4* hb4 = reinterpret_cast<const uint4*>(g_hbf[t & 1]);
        uint64_t hreg[32];
#pragma unroll
        for (int k4 = 0; k4 < 8; k4++) {
            uint4 hv = __ldcv(hb4 + 32 * k4 + lane);
            hreg[4 * k4 + 0] = bf2f32x2(hv.x);
            hreg[4 * k4 + 1] = bf2f32x2(hv.y);
            hreg[4 * k4 + 2] = bf2f32x2(hv.z);
            hreg[4 * k4 + 3] = bf2f32x2(hv.w);
        }

        // --- row dots: LDS.128 weights + FFMA2, 4 independent packed chains ---
        float dots[7];
#pragma unroll
        for (int r = 0; r < 7; r++) {
            float d = 0.f;
            if (r < nrows) {
                const uint4* w4 = ws4 + woff4[r];
                uint64_t a0 = 0, a1 = 0, a2 = 0, a3 = 0;
#pragma unroll
                for (int k4 = 0; k4 < 8; k4++) {
                    uint4 w = w4[32 * k4 + lane];
                    a0 = fma2(bf2f32x2(w.x), hreg[4 * k4 + 0], a0);
                    a1 = fma2(bf2f32x2(w.y), hreg[4 * k4 + 1], a1);
                    a2 = fma2(bf2f32x2(w.z), hreg[4 * k4 + 2], a2);
                    a3 = fma2(bf2f32x2(w.w), hreg[4 * k4 + 3], a3);
                }
                d = (f32x2sum(a0) + f32x2sum(a1)) + (f32x2sum(a2) + f32x2sum(a3));
            }
            dots[r] = d;
        }

        // --- interleaved butterfly reductions (7 independent trees) ---
#pragma unroll
        for (int o = 16; o; o >>= 1) {
#pragma unroll
            for (int r = 0; r < 7; r++)
                dots[r] += __shfl_xor_sync(0xffffffffu, dots[r], o);
        }
        if (lane == 0) {
#pragma unroll
            for (int r = 0; r < 7; r++)
                if (r < nrows) gates_sm[pidx[r]] = dots[r] + xgv[r];
        }
        __syncthreads();

        // --- cell update (warp 0) + output partial ---
        if (warp == 0) {
            float pv = 0.f;
            if (lane < J) {
                float iv = gates_sm[lane];
                float fv = gates_sm[J + lane];
                float gv = gates_sm[2 * J + lane];
                float ov = gates_sm[3 * J + lane];
                float c  = c_sm[lane];
                float cn = sigf(fv) * c + sigf(iv) * tanhf(gv);
                float hn = sigf(ov) * tanhf(cn);
                c_sm[lane] = cn;
                g_hbf[(t & 1) ^ 1][base + lane] = __float2bfloat16_rn(hn);
                pv = hn * wout;
            }
#pragma unroll
            for (int o = 16; o; o >>= 1) pv += __shfl_xor_sync(0xffffffffu, pv, o);
            if (lane == 0) g_partial[(size_t)t * MAXB + b] = pv;
        }

        // --- prefetch next step's xg while others finish / before barrier ---
        if (t + 1 < T_STEPS) {
            const float* xr = g_XG + (size_t)(t + 1) * G_DIM;
#pragma unroll
            for (int r = 0; r < 7; r++)
                if (r < nrows) xgv[r] = __ldg(xr + xgcol[r]);
        }

        __syncthreads();   // all h stores of this CTA done before arrival

        // --- grid barrier: release arrival, acquire polling (no atomic spin) ---
        if (t < T_STEPS - 1) {
            if (tid == 0) {
                const unsigned target = (unsigned)nb * (unsigned)(t + 1);
                asm volatile("red.release.gpu.global.add.u32 [%0], 1;"
                             :: "l"(&g_bar) : "memory");
                unsigned v;
                do {
                    asm volatile("ld.acquire.gpu.global.u32 %0, [%1];"
                                 : "=r"(v) : "l"(&g_bar) : "memory");
                } while (v < target);
            }
            __syncthreads();
        }
    }
}

// ---------------------------------------------------------------------------
// Kernel 4: out[t] = b_out + sum_b partial[t][b]  (fixed order, deterministic)
// ---------------------------------------------------------------------------
__global__ void reduce_out(const float* __restrict__ bo, float* __restrict__ out, int nb) {
    int t = blockIdx.x * blockDim.x + threadIdx.x;
    if (t >= T_STEPS) return;
    float s = bo[0];
    const float* p = g_partial + (size_t)t * MAXB;
    for (int b = 0; b < nb; b++) s += p[b];
    out[t] = s;
}

// ---------------------------------------------------------------------------
// Host launcher (graph-capturable: kernels + async memsets only)
// ---------------------------------------------------------------------------
extern "C" void kernel_launch(void* const* d_in, const int* in_sizes, int n_in,
                              void* d_out, int out_size)
{
    const float* input = (const float*)d_in[0];   // [T, 1, F]
    const float* W_ih  = (const float*)d_in[1];   // [4H, F]
    const float* W_hh  = (const float*)d_in[2];   // [4H, H]
    const float* b_ih  = (const float*)d_in[3];
    const float* b_hh  = (const float*)d_in[4];
    const float* W_out = (const float*)d_in[5];   // [1, H]
    const float* b_out = (const float*)d_in[6];
    float* out = (float*)d_out;                   // [T, 1, 1]

    int dev = 0;
    cudaGetDevice(&dev);
    int nsm = 148;
    cudaDeviceGetAttribute(&nsm, cudaDevAttrMultiProcessorCount, dev);
    int nb = nsm;
    if (nb > MAXB) nb = MAXB;
    if (nb > H_DIM) nb = H_DIM;

    const int Jmax = (H_DIM + nb - 1) / nb;                       // 14 @ 152 SMs
    const size_t smem = (size_t)4 * Jmax * 256 * sizeof(uint4);   // 229376 B

    cudaFuncSetAttribute(lstm_kernel, cudaFuncAttributeMaxDynamicSharedMemorySize, (int)smem);

    void* barp = nullptr; cudaGetSymbolAddress(&barp, g_bar);
    void* hptr = nullptr; cudaGetSymbolAddress(&hptr, g_hbf);
    cudaMemsetAsync(barp, 0, sizeof(unsigned));
    cudaMemsetAsync(hptr, 0, 2 * H_DIM * sizeof(__nv_bfloat16));

    convert_whh<<<(G_DIM * H_DIM / 4 + 255) / 256, 256>>>(W_hh);

    dim3 ggrid(G_DIM / 128, T_STEPS / 128);
    gemm_xg<<<ggrid, 256>>>(input, W_ih, b_ih, b_hh);

    lstm_kernel<<<nb, 256, smem>>>(W_out, nb);

    reduce_out<<<(T_STEPS + 255) / 256, 256>>>(b_out, out, nb);
}

// round 7
// speedup vs baseline: 2.0019x; 1.3299x over previous
#include <cuda_runtime.h>
#include <cuda_bf16.h>
#include <cstdint>
#include <cstddef>

#define T_STEPS 8192
#define F_DIM   1024
#define H_DIM   2048
#define G_DIM   (4 * H_DIM)   // 8192 gate rows
#define MAXB    256

// ---------------------------------------------------------------------------
// Static device scratch (no cudaMalloc anywhere)
// ---------------------------------------------------------------------------
__device__ float                         g_XG[(size_t)T_STEPS * G_DIM];   // x-gates, 256 MB
__device__ __nv_bfloat16                 g_Whh[(size_t)G_DIM * H_DIM];    // bf16 W_hh, 32 MB
__device__ __align__(16) __nv_bfloat16   g_hbf[2][H_DIM];                 // double-buffered h (bf16)
__device__ float                         g_partial[(size_t)T_STEPS * MAXB];
__device__ unsigned                      g_bar;

// ---------------------------------------------------------------------------
// Helpers
// ---------------------------------------------------------------------------
__device__ __forceinline__ uint64_t bf2f32x2(unsigned u) {
    unsigned lo = u << 16;
    unsigned hi = u & 0xffff0000u;
    uint64_t r;
    asm("mov.b64 %0, {%1, %2};" : "=l"(r) : "r"(lo), "r"(hi));
    return r;
}
__device__ __forceinline__ uint64_t fma2(uint64_t a, uint64_t b, uint64_t c) {
    uint64_t d;
    asm("fma.rn.f32x2 %0, %1, %2, %3;" : "=l"(d) : "l"(a), "l"(b), "l"(c));
    return d;
}
__device__ __forceinline__ float f32x2sum(uint64_t a) {
    float x, y;
    asm("mov.b64 {%0, %1}, %2;" : "=f"(x), "=f"(y) : "l"(a));
    return x + y;
}
__device__ __forceinline__ float sigf(float x) { return 1.f / (1.f + __expf(-x)); }
__device__ __forceinline__ float tanh_fast(float x) {
    float y; asm("tanh.approx.f32 %0, %1;" : "=f"(y) : "f"(x)); return y;
}

// ---------------------------------------------------------------------------
// Kernel 1: convert W_hh fp32 -> bf16
// ---------------------------------------------------------------------------
__global__ void convert_whh(const float* __restrict__ W) {
    int i = blockIdx.x * blockDim.x + threadIdx.x;     // one float4 per thread
    const int n4 = (G_DIM * H_DIM) / 4;
    if (i >= n4) return;
    float4 v = reinterpret_cast<const float4*>(W)[i];
    __nv_bfloat162* o = reinterpret_cast<__nv_bfloat162*>(g_Whh);
    o[i * 2 + 0] = __floats2bfloat162_rn(v.x, v.y);
    o[i * 2 + 1] = __floats2bfloat162_rn(v.z, v.w);
}

// ---------------------------------------------------------------------------
// Kernel 2: XG[t,g] = X[t,:] . Wih[g,:] + b_ih[g] + b_hh[g]  (fp32 SGEMM)
// ---------------------------------------------------------------------------
__global__ __launch_bounds__(256, 2) void gemm_xg(
    const float* __restrict__ X,    // [T, F]
    const float* __restrict__ Wih,  // [G, F]
    const float* __restrict__ bi,
    const float* __restrict__ bh)
{
    __shared__ __align__(16) float As[16][128];
    __shared__ __align__(16) float Bs[16][128];

    const int bm = blockIdx.y * 128;   // t
    const int bn = blockIdx.x * 128;   // g
    const int tid = threadIdx.x;
    const int tx = tid & 15, ty = tid >> 4;
    const int lr = tid >> 1, lc = (tid & 1) << 3;

    float acc[8][8];
#pragma unroll
    for (int i = 0; i < 8; i++)
#pragma unroll
        for (int j = 0; j < 8; j++) acc[i][j] = 0.f;

    const float4* Ag = reinterpret_cast<const float4*>(X   + (size_t)(bm + lr) * F_DIM + lc);
    const float4* Bg = reinterpret_cast<const float4*>(Wih + (size_t)(bn + lr) * F_DIM + lc);

    for (int k0 = 0; k0 < F_DIM; k0 += 16) {
        float4 a0 = Ag[0], a1 = Ag[1];
        float4 b0 = Bg[0], b1 = Bg[1];
        Ag += 4; Bg += 4;
        __syncthreads();
        As[lc + 0][lr] = a0.x; As[lc + 1][lr] = a0.y; As[lc + 2][lr] = a0.z; As[lc + 3][lr] = a0.w;
        As[lc + 4][lr] = a1.x; As[lc + 5][lr] = a1.y; As[lc + 6][lr] = a1.z; As[lc + 7][lr] = a1.w;
        Bs[lc + 0][lr] = b0.x; Bs[lc + 1][lr] = b0.y; Bs[lc + 2][lr] = b0.z; Bs[lc + 3][lr] = b0.w;
        Bs[lc + 4][lr] = b1.x; Bs[lc + 5][lr] = b1.y; Bs[lc + 6][lr] = b1.z; Bs[lc + 7][lr] = b1.w;
        __syncthreads();
#pragma unroll
        for (int kk = 0; kk < 16; kk++) {
            float4 af0 = *reinterpret_cast<const float4*>(&As[kk][ty * 8]);
            float4 af1 = *reinterpret_cast<const float4*>(&As[kk][ty * 8 + 4]);
            float4 bf0 = *reinterpret_cast<const float4*>(&Bs[kk][tx * 8]);
            float4 bf1 = *reinterpret_cast<const float4*>(&Bs[kk][tx * 8 + 4]);
            float a[8] = {af0.x, af0.y, af0.z, af0.w, af1.x, af1.y, af1.z, af1.w};
            float b[8] = {bf0.x, bf0.y, bf0.z, bf0.w, bf1.x, bf1.y, bf1.z, bf1.w};
#pragma unroll
            for (int i = 0; i < 8; i++)
#pragma unroll
                for (int j = 0; j < 8; j++) acc[i][j] += a[i] * b[j];
        }
    }

    float bb[8];
#pragma unroll
    for (int j = 0; j < 8; j++) {
        int g = bn + tx * 8 + j;
        bb[j] = bi[g] + bh[g];
    }
#pragma unroll
    for (int i = 0; i < 8; i++) {
        size_t row = (size_t)(bm + ty * 8 + i) * G_DIM + bn + tx * 8;
        float4 o0 = make_float4(acc[i][0] + bb[0], acc[i][1] + bb[1],
                                acc[i][2] + bb[2], acc[i][3] + bb[3]);
        float4 o1 = make_float4(acc[i][4] + bb[4], acc[i][5] + bb[5],
                                acc[i][6] + bb[6], acc[i][7] + bb[7]);
        reinterpret_cast<float4*>(g_XG + row)[0] = o0;
        reinterpret_cast<float4*>(g_XG + row)[1] = o1;
    }
}

// ---------------------------------------------------------------------------
// Kernel 3: persistent LSTM recurrence.
// One CTA per SM; 4*J W_hh rows split: k[0,1024) in REGISTERS (112 u32/thread),
// k[1024,2048) in SMEM. h broadcast staged through SMEM (one L2 uint4/thread).
// ---------------------------------------------------------------------------
__global__ __launch_bounds__(256, 1) void lstm_kernel(
    const float* __restrict__ Wout, int nb)
{
    extern __shared__ uint4 dsm[];          // [0,256): h_sm ; [256, ...): weight half B
    uint4* h_sm = dsm;                      // 256 uint4 = 2048 bf16
    uint4* wsm  = dsm + 256;                // 4*J rows x 128 uint4 (k half B)
    __shared__ float gates_sm[64];
    __shared__ float c_sm[16];

    const int tid  = threadIdx.x;
    const int lane = tid & 31;
    const int warp = tid >> 5;              // 8 warps
    const int b    = blockIdx.x;

    const int base = (b * H_DIM) / nb;
    const int J    = ((b + 1) * H_DIM) / nb - base;   // 13 or 14

    const uint4* whh4 = reinterpret_cast<const uint4*>(g_Whh);  // 256 uint4 per row

    // per-warp row metadata
    int nrows = 0;
    int xgcol[7], pidx[7];
#pragma unroll
    for (int r = 0; r < 7; r++) { xgcol[r] = 0; pidx[r] = 0; }
    for (int p = warp; p < 4 * J; p += 8) {
        int q = p / J, jj = p - q * J;
        xgcol[nrows] = q * H_DIM + base + jj;   // global gate-row index
        pidx[nrows]  = p;
        nrows++;
    }

    // --- stage weight half B (k in [1024,2048)) into SMEM ---
    {
        const int totw = 4 * J * 128;
        for (int i = tid; i < totw; i += 256) {
            int p = i >> 7, o = i & 127;
            int q = p / J, jj = p - q * J;
            size_t row = (size_t)q * H_DIM + base + jj;
            wsm[i] = whh4[row * 256 + 128 + o];
        }
    }

    // --- weight half A (k in [0,1024)) into registers: 7 rows x 4 uint4 ---
    uint4 wreg[7][4];
#pragma unroll
    for (int r = 0; r < 7; r++) {
#pragma unroll
        for (int k4 = 0; k4 < 4; k4++) {
            uint4 z = make_uint4(0u, 0u, 0u, 0u);
            wreg[r][k4] = (r < nrows)
                ? whh4[(size_t)xgcol[r] * 256 + 32 * k4 + lane] : z;
        }
    }

    if (tid < J) c_sm[tid] = 0.f;
    const float wout = (warp == 0 && lane < J) ? Wout[base + lane] : 0.f;
    __syncthreads();

    // prefetch xg for t = 0
    float xgv[7];
#pragma unroll
    for (int r = 0; r < 7; r++) xgv[r] = (r < nrows) ? __ldg(g_XG + xgcol[r]) : 0.f;

    for (int t = 0; t < T_STEPS; t++) {
        // --- stage h (bf16) into SMEM: one uint4 per thread, L2 (.cg) ---
        {
            const uint4* hg = reinterpret_cast<const uint4*>(g_hbf[t & 1]);
            h_sm[tid] = __ldcg(hg + tid);
        }
        __syncthreads();

        float dots[7];
        uint64_t hreg[16];

        // ===== half A: k in [0,1024), weights in registers =====
#pragma unroll
        for (int k4 = 0; k4 < 4; k4++) {
            uint4 hv = h_sm[32 * k4 + lane];
            hreg[4 * k4 + 0] = bf2f32x2(hv.x);
            hreg[4 * k4 + 1] = bf2f32x2(hv.y);
            hreg[4 * k4 + 2] = bf2f32x2(hv.z);
            hreg[4 * k4 + 3] = bf2f32x2(hv.w);
        }
#pragma unroll
        for (int r = 0; r < 7; r++) {
            uint64_t a0 = 0, a1 = 0, a2 = 0, a3 = 0;
#pragma unroll
            for (int k4 = 0; k4 < 4; k4++) {
                uint4 w = wreg[r][k4];
                a0 = fma2(bf2f32x2(w.x), hreg[4 * k4 + 0], a0);
                a1 = fma2(bf2f32x2(w.y), hreg[4 * k4 + 1], a1);
                a2 = fma2(bf2f32x2(w.z), hreg[4 * k4 + 2], a2);
                a3 = fma2(bf2f32x2(w.w), hreg[4 * k4 + 3], a3);
            }
            dots[r] = (f32x2sum(a0) + f32x2sum(a1)) + (f32x2sum(a2) + f32x2sum(a3));
        }

        // ===== half B: k in [1024,2048), weights in SMEM =====
#pragma unroll
        for (int k4 = 0; k4 < 4; k4++) {
            uint4 hv = h_sm[128 + 32 * k4 + lane];
            hreg[4 * k4 + 0] = bf2f32x2(hv.x);
            hreg[4 * k4 + 1] = bf2f32x2(hv.y);
            hreg[4 * k4 + 2] = bf2f32x2(hv.z);
            hreg[4 * k4 + 3] = bf2f32x2(hv.w);
        }
#pragma unroll
        for (int r = 0; r < 7; r++) {
            if (r < nrows) {
                const uint4* wrow = wsm + pidx[r] * 128;
                uint64_t a0 = 0, a1 = 0, a2 = 0, a3 = 0;
#pragma unroll
                for (int k4 = 0; k4 < 4; k4++) {
                    uint4 w = wrow[32 * k4 + lane];
                    a0 = fma2(bf2f32x2(w.x), hreg[4 * k4 + 0], a0);
                    a1 = fma2(bf2f32x2(w.y), hreg[4 * k4 + 1], a1);
                    a2 = fma2(bf2f32x2(w.z), hreg[4 * k4 + 2], a2);
                    a3 = fma2(bf2f32x2(w.w), hreg[4 * k4 + 3], a3);
                }
                dots[r] += (f32x2sum(a0) + f32x2sum(a1)) + (f32x2sum(a2) + f32x2sum(a3));
            }
        }

        // --- interleaved butterfly reductions (7 independent trees) ---
#pragma unroll
        for (int o = 16; o; o >>= 1) {
#pragma unroll
            for (int r = 0; r < 7; r++)
                dots[r] += __shfl_xor_sync(0xffffffffu, dots[r], o);
        }
        if (lane == 0) {
#pragma unroll
            for (int r = 0; r < 7; r++)
                if (r < nrows) gates_sm[pidx[r]] = dots[r] + xgv[r];
        }
        __syncthreads();

        // --- cell update (warp 0) -> publish h slice ---
        float hn = 0.f;
        if (warp == 0 && lane < J) {
            float iv = gates_sm[lane];
            float fv = gates_sm[J + lane];
            float gv = gates_sm[2 * J + lane];
            float ov = gates_sm[3 * J + lane];
            float c  = c_sm[lane];
            float cn = sigf(fv) * c + sigf(iv) * tanh_fast(gv);
            hn = sigf(ov) * tanh_fast(cn);
            c_sm[lane] = cn;
            g_hbf[(t & 1) ^ 1][base + lane] = __float2bfloat16_rn(hn);
        }
        __syncthreads();   // h store + all h_sm reads of this step complete

        // --- barrier arrival ASAP (release orders prior stores) ---
        if (t < T_STEPS - 1 && tid == 0) {
            asm volatile("red.release.gpu.global.add.u32 [%0], 1;"
                         :: "l"(&g_bar) : "memory");
        }

        // --- shadow work hidden under barrier propagation ---
        if (warp == 0) {
            float pv = hn * wout;
#pragma unroll
            for (int o = 16; o; o >>= 1) pv += __shfl_xor_sync(0xffffffffu, pv, o);
            if (lane == 0) g_partial[(size_t)t * MAXB + b] = pv;
        }
        if (t + 1 < T_STEPS) {
            const float* xr = g_XG + (size_t)(t + 1) * G_DIM;
#pragma unroll
            for (int r = 0; r < 7; r++)
                if (r < nrows) xgv[r] = __ldg(xr + xgcol[r]);
        }

        // --- barrier wait ---
        if (t < T_STEPS - 1) {
            if (tid == 0) {
                const unsigned target = (unsigned)nb * (unsigned)(t + 1);
                unsigned v;
                do {
                    asm volatile("ld.acquire.gpu.global.u32 %0, [%1];"
                                 : "=r"(v) : "l"(&g_bar) : "memory");
                } while (v < target);
            }
            __syncthreads();
        }
    }
}

// ---------------------------------------------------------------------------
// Kernel 4: out[t] = b_out + sum_b partial[t][b]  (fixed order, deterministic)
// ---------------------------------------------------------------------------
__global__ void reduce_out(const float* __restrict__ bo, float* __restrict__ out, int nb) {
    int t = blockIdx.x * blockDim.x + threadIdx.x;
    if (t >= T_STEPS) return;
    float s = bo[0];
    const float* p = g_partial + (size_t)t * MAXB;
    for (int b = 0; b < nb; b++) s += p[b];
    out[t] = s;
}

// ---------------------------------------------------------------------------
// Host launcher (graph-capturable: kernels + async memsets only)
// ---------------------------------------------------------------------------
extern "C" void kernel_launch(void* const* d_in, const int* in_sizes, int n_in,
                              void* d_out, int out_size)
{
    const float* input = (const float*)d_in[0];   // [T, 1, F]
    const float* W_ih  = (const float*)d_in[1];   // [4H, F]
    const float* W_hh  = (const float*)d_in[2];   // [4H, H]
    const float* b_ih  = (const float*)d_in[3];
    const float* b_hh  = (const float*)d_in[4];
    const float* W_out = (const float*)d_in[5];   // [1, H]
    const float* b_out = (const float*)d_in[6];
    float* out = (float*)d_out;                   // [T, 1, 1]

    int dev = 0;
    cudaGetDevice(&dev);
    int nsm = 148;
    cudaDeviceGetAttribute(&nsm, cudaDevAttrMultiProcessorCount, dev);
    int nb = nsm;
    if (nb > MAXB) nb = MAXB;
    if (nb > H_DIM) nb = H_DIM;

    const int Jmax = (H_DIM + nb - 1) / nb;       // 14 @ 152 SMs
    // smem: 256 uint4 (h) + 4*Jmax*128 uint4 (weight half B)
    const size_t smem = (size_t)(256 + 4 * Jmax * 128) * sizeof(uint4);  // 118784 B

    cudaFuncSetAttribute(lstm_kernel, cudaFuncAttributeMaxDynamicSharedMemorySize, (int)smem);

    void* barp = nullptr; cudaGetSymbolAddress(&barp, g_bar);
    void* hptr = nullptr; cudaGetSymbolAddress(&hptr, g_hbf);
    cudaMemsetAsync(barp, 0, sizeof(unsigned));
    cudaMemsetAsync(hptr, 0, 2 * H_DIM * sizeof(__nv_bfloat16));

    convert_whh<<<(G_DIM * H_DIM / 4 + 255) / 256, 256>>>(W_hh);

    dim3 ggrid(G_DIM / 128, T_STEPS / 128);
    gemm_xg<<<ggrid, 256>>>(input, W_ih, b_ih, b_hh);

    lstm_kernel<<<nb, 256, smem>>>(W_out, nb);

    reduce_out<<<(T_STEPS + 255) / 256, 256>>>(b_out, out, nb);
}

// round 9
// speedup vs baseline: 2.7466x; 1.3720x over previous
#include <cuda_runtime.h>
#include <cuda_fp16.h>
#include <cstdint>
#include <cstddef>

#define T_STEPS 8192
#define F_DIM   1024
#define H_DIM   2048
#define G_DIM   (4 * H_DIM)
#define MAXB    256
#define NB      128            // persistent CTAs: 16 hidden units / 64 gate rows each

// ---------------------------------------------------------------------------
// Static device scratch (no cudaMalloc anywhere)
// ---------------------------------------------------------------------------
__device__ float                    g_XG[(size_t)T_STEPS * G_DIM];   // x-gates, 256 MB
__device__ __half                   g_Whf[(size_t)G_DIM * H_DIM];    // fp16 W_hh, 32 MB
__device__ __align__(16) __half     g_hf[2][H_DIM];                  // double-buffered h (fp16)
__device__ float                    g_partial[(size_t)T_STEPS * MAXB];
__device__ unsigned                 g_bar;

// ---------------------------------------------------------------------------
// Helpers
// ---------------------------------------------------------------------------
__device__ __forceinline__ __half2 u2h(unsigned x) {
    __half2 h; *reinterpret_cast<unsigned*>(&h) = x; return h;
}
__device__ __forceinline__ void mac4(uint4 w, uint4 h, __half2& acc) {
    acc = __hfma2(u2h(w.x), u2h(h.x), acc);
    acc = __hfma2(u2h(w.y), u2h(h.y), acc);
    acc = __hfma2(u2h(w.z), u2h(h.z), acc);
    acc = __hfma2(u2h(w.w), u2h(h.w), acc);
}
__device__ __forceinline__ void flush(__half2& acc, float& fa, float& fb) {
    float2 f = __half22float2(acc);
    fa += f.x; fb += f.y;
    acc = __half2half2(__ushort_as_half(0));
}
__device__ __forceinline__ float sigf(float x) { return 1.f / (1.f + __expf(-x)); }
__device__ __forceinline__ float tanh_fast(float x) {
    float y; asm("tanh.approx.f32 %0, %1;" : "=f"(y) : "f"(x)); return y;
}

// ---------------------------------------------------------------------------
// Kernel 1: convert W_hh fp32 -> fp16
// ---------------------------------------------------------------------------
__global__ void convert_whh(const float* __restrict__ W) {
    int i = blockIdx.x * blockDim.x + threadIdx.x;     // one float4 per thread
    const int n4 = (G_DIM * H_DIM) / 4;
    if (i >= n4) return;
    float4 v = reinterpret_cast<const float4*>(W)[i];
    __half2* o = reinterpret_cast<__half2*>(g_Whf);
    o[i * 2 + 0] = __floats2half2_rn(v.x, v.y);
    o[i * 2 + 1] = __floats2half2_rn(v.z, v.w);
}

// ---------------------------------------------------------------------------
// Kernel 2: XG = X @ W_ih^T + b_ih + b_hh  (fp32 SGEMM, unchanged)
// ---------------------------------------------------------------------------
__global__ __launch_bounds__(256, 2) void gemm_xg(
    const float* __restrict__ X, const float* __restrict__ Wih,
    const float* __restrict__ bi, const float* __restrict__ bh)
{
    __shared__ __align__(16) float As[16][128];
    __shared__ __align__(16) float Bs[16][128];

    const int bm = blockIdx.y * 128;
    const int bn = blockIdx.x * 128;
    const int tid = threadIdx.x;
    const int tx = tid & 15, ty = tid >> 4;
    const int lr = tid >> 1, lc = (tid & 1) << 3;

    float acc[8][8];
#pragma unroll
    for (int i = 0; i < 8; i++)
#pragma unroll
        for (int j = 0; j < 8; j++) acc[i][j] = 0.f;

    const float4* Ag = reinterpret_cast<const float4*>(X   + (size_t)(bm + lr) * F_DIM + lc);
    const float4* Bg = reinterpret_cast<const float4*>(Wih + (size_t)(bn + lr) * F_DIM + lc);

    for (int k0 = 0; k0 < F_DIM; k0 += 16) {
        float4 a0 = Ag[0], a1 = Ag[1];
        float4 b0 = Bg[0], b1 = Bg[1];
        Ag += 4; Bg += 4;
        __syncthreads();
        As[lc + 0][lr] = a0.x; As[lc + 1][lr] = a0.y; As[lc + 2][lr] = a0.z; As[lc + 3][lr] = a0.w;
        As[lc + 4][lr] = a1.x; As[lc + 5][lr] = a1.y; As[lc + 6][lr] = a1.z; As[lc + 7][lr] = a1.w;
        Bs[lc + 0][lr] = b0.x; Bs[lc + 1][lr] = b0.y; Bs[lc + 2][lr] = b0.z; Bs[lc + 3][lr] = b0.w;
        Bs[lc + 4][lr] = b1.x; Bs[lc + 5][lr] = b1.y; Bs[lc + 6][lr] = b1.z; Bs[lc + 7][lr] = b1.w;
        __syncthreads();
#pragma unroll
        for (int kk = 0; kk < 16; kk++) {
            float4 af0 = *reinterpret_cast<const float4*>(&As[kk][ty * 8]);
            float4 af1 = *reinterpret_cast<const float4*>(&As[kk][ty * 8 + 4]);
            float4 bf0 = *reinterpret_cast<const float4*>(&Bs[kk][tx * 8]);
            float4 bf1 = *reinterpret_cast<const float4*>(&Bs[kk][tx * 8 + 4]);
            float a[8] = {af0.x, af0.y, af0.z, af0.w, af1.x, af1.y, af1.z, af1.w};
            float b[8] = {bf0.x, bf0.y, bf0.z, bf0.w, bf1.x, bf1.y, bf1.z, bf1.w};
#pragma unroll
            for (int i = 0; i < 8; i++)
#pragma unroll
                for (int j = 0; j < 8; j++) acc[i][j] += a[i] * b[j];
        }
    }

    float bb[8];
#pragma unroll
    for (int j = 0; j < 8; j++) {
        int g = bn + tx * 8 + j;
        bb[j] = bi[g] + bh[g];
    }
#pragma unroll
    for (int i = 0; i < 8; i++) {
        size_t row = (size_t)(bm + ty * 8 + i) * G_DIM + bn + tx * 8;
        float4 o0 = make_float4(acc[i][0] + bb[0], acc[i][1] + bb[1],
                                acc[i][2] + bb[2], acc[i][3] + bb[3]);
        float4 o1 = make_float4(acc[i][4] + bb[4], acc[i][5] + bb[5],
                                acc[i][6] + bb[6], acc[i][7] + bb[7]);
        reinterpret_cast<float4*>(g_XG + row)[0] = o0;
        reinterpret_cast<float4*>(g_XG + row)[1] = o1;
    }
}

// ---------------------------------------------------------------------------
// Kernel 3: persistent HFMA2 LSTM recurrence.
// 128 CTAs x 256 threads. Each CTA: 64 gate rows (16 hidden units).
// Warp w owns rows [8w, 8w+8). k[0,1024): weights in registers (32 uint4),
// k[1024,2048): weights in SMEM. fp16x2 MACs, depth-8 chunks flushed to fp32.
// ---------------------------------------------------------------------------
__global__ __launch_bounds__(256, 1) void lstm_kernel(
    const float* __restrict__ Wout)
{
    extern __shared__ uint4 wsm[];        // 64 rows x 128 uint4 (k half B) = 128 KB
    __shared__ uint4  h_sm4[256];         // h staged, 2048 fp16
    __shared__ float  gates_sm[64];
    __shared__ float  xg_sm[64];

    const int tid  = threadIdx.x;
    const int lane = tid & 31;
    const int wid  = tid >> 5;            // 8 warps
    const int b    = blockIdx.x;
    const int base = b * 16;              // first hidden unit of this CTA

    const uint4* whh4 = reinterpret_cast<const uint4*>(g_Whf);  // 256 uint4 per gate row

    // global gate-row index for CTA-local row m
    auto grow = [&](int m) -> size_t {
        return (size_t)(m >> 4) * H_DIM + base + (m & 15);
    };

    // ---- stage SMEM weights: k half B (uint4 idx 128..255 of each row) ----
    for (int i = tid; i < 64 * 128; i += 256) {
        int m = i >> 7, o = i & 127;
        wsm[i] = __ldg(whh4 + grow(m) * 256 + 128 + o);
    }

    // ---- register weights: k half A, rows 8*wid..8*wid+7, 4 uint4 each ----
    uint4 wreg[8][4];
#pragma unroll
    for (int r = 0; r < 8; r++) {
        size_t g = grow(wid * 8 + r) * 256;
#pragma unroll
        for (int c = 0; c < 4; c++)
            wreg[r][c] = __ldg(whh4 + g + 32 * c + lane);
    }

    float creg = 0.f;
    const float wout = (wid == 0 && lane < 16) ? Wout[base + lane] : 0.f;

    // xg preload for t = 0 (warps 0,1 cover 64 rows)
    if (wid < 2) {
        int m = wid * 32 + lane;
        xg_sm[m] = __ldg(g_XG + grow(m));
    }
    __syncthreads();

    const int myrow0 = wid * 8;

    for (int t = 0; t < T_STEPS; t++) {
        // ---- stage h (fp16): one uint4 per thread, L2 (.cg) ----
        {
            const uint4* hg = reinterpret_cast<const uint4*>(g_hf[t & 1]);
            h_sm4[tid] = __ldcg(hg + tid);
        }
        __syncthreads();

        float dots[8];

        // ===== half A: k in [0,1024), register weights =====
        {
            uint4 h0 = h_sm4[lane];
            uint4 h1 = h_sm4[32 + lane];
            uint4 h2 = h_sm4[64 + lane];
            uint4 h3 = h_sm4[96 + lane];
#pragma unroll
            for (int r = 0; r < 8; r++) {
                __half2 acc = __half2half2(__ushort_as_half(0));
                float fa = 0.f, fb = 0.f;
                mac4(wreg[r][0], h0, acc);
                mac4(wreg[r][1], h1, acc);
                flush(acc, fa, fb);
                mac4(wreg[r][2], h2, acc);
                mac4(wreg[r][3], h3, acc);
                flush(acc, fa, fb);
                dots[r] = fa + fb;
            }
        }

        // ===== half B: k in [1024,2048), SMEM weights =====
        {
            uint4 h0 = h_sm4[128 + lane];
            uint4 h1 = h_sm4[160 + lane];
            uint4 h2 = h_sm4[192 + lane];
            uint4 h3 = h_sm4[224 + lane];
            const uint4* wrow = wsm + myrow0 * 128;
#pragma unroll
            for (int r = 0; r < 8; r++) {
                uint4 w0 = wrow[r * 128 + lane];
                uint4 w1 = wrow[r * 128 + 32 + lane];
                uint4 w2 = wrow[r * 128 + 64 + lane];
                uint4 w3 = wrow[r * 128 + 96 + lane];
                __half2 acc = __half2half2(__ushort_as_half(0));
                float fa = 0.f, fb = 0.f;
                mac4(w0, h0, acc);
                mac4(w1, h1, acc);
                flush(acc, fa, fb);
                mac4(w2, h2, acc);
                mac4(w3, h3, acc);
                flush(acc, fa, fb);
                dots[r] += fa + fb;
            }
        }

        // ---- interleaved butterfly reductions (8 independent trees) ----
#pragma unroll
        for (int o = 16; o; o >>= 1) {
#pragma unroll
            for (int r = 0; r < 8; r++)
                dots[r] += __shfl_xor_sync(0xffffffffu, dots[r], o);
        }
        if (lane == 0) {
#pragma unroll
            for (int r = 0; r < 8; r++) gates_sm[myrow0 + r] = dots[r];
        }
        __syncthreads();

        // ---- activations (warp 0, lanes 0-15) + h publish ----
        float hn = 0.f;
        if (wid == 0 && lane < 16) {
            float iv = gates_sm[lane]      + xg_sm[lane];
            float fv = gates_sm[16 + lane] + xg_sm[16 + lane];
            float gv = gates_sm[32 + lane] + xg_sm[32 + lane];
            float ov = gates_sm[48 + lane] + xg_sm[48 + lane];
            float cn = sigf(fv) * creg + sigf(iv) * tanh_fast(gv);
            hn = sigf(ov) * tanh_fast(cn);
            creg = cn;
            g_hf[(t + 1) & 1][base + lane] = __float2half_rn(hn);
        }
        __syncthreads();   // h stores done; gates/xg consumed

        // ---- barrier arrival ASAP (release orders prior stores) ----
        if (t < T_STEPS - 1 && tid == 0) {
            asm volatile("red.release.gpu.global.add.u32 [%0], 1;"
                         :: "l"(&g_bar) : "memory");
        }

        // ---- shadow work hidden under barrier propagation ----
        if (wid == 0) {
            float pv = hn * wout;
#pragma unroll
            for (int o = 16; o; o >>= 1) pv += __shfl_xor_sync(0xffffffffu, pv, o);
            if (lane == 0) g_partial[(size_t)t * MAXB + b] = pv;
        }
        if (wid < 2 && t + 1 < T_STEPS) {
            int m = wid * 32 + lane;
            xg_sm[m] = __ldg(g_XG + (size_t)(t + 1) * G_DIM + grow(m));
        }

        // ---- barrier wait ----
        if (t < T_STEPS - 1) {
            if (tid == 0) {
                const unsigned target = (unsigned)NB * (unsigned)(t + 1);
                unsigned v;
                do {
                    asm volatile("ld.acquire.gpu.global.u32 %0, [%1];"
                                 : "=r"(v) : "l"(&g_bar) : "memory");
                } while (v < target);
            }
            __syncthreads();
        }
    }
}

// ---------------------------------------------------------------------------
// Kernel 4: out[t] = b_out + sum_b partial[t][b]  (fixed order, deterministic)
// ---------------------------------------------------------------------------
__global__ void reduce_out(const float* __restrict__ bo, float* __restrict__ out) {
    int t = blockIdx.x * blockDim.x + threadIdx.x;
    if (t >= T_STEPS) return;
    float s = bo[0];
    const float* p = g_partial + (size_t)t * MAXB;
    for (int b = 0; b < NB; b++) s += p[b];
    out[t] = s;
}

// ---------------------------------------------------------------------------
// Host launcher (graph-capturable: kernels + async memsets only)
// ---------------------------------------------------------------------------
extern "C" void kernel_launch(void* const* d_in, const int* in_sizes, int n_in,
                              void* d_out, int out_size)
{
    const float* input = (const float*)d_in[0];   // [T, 1, F]
    const float* W_ih  = (const float*)d_in[1];   // [4H, F]
    const float* W_hh  = (const float*)d_in[2];   // [4H, H]
    const float* b_ih  = (const float*)d_in[3];
    const float* b_hh  = (const float*)d_in[4];
    const float* W_out = (const float*)d_in[5];   // [1, H]
    const float* b_out = (const float*)d_in[6];
    float* out = (float*)d_out;                   // [T, 1, 1]

    const size_t smem = (size_t)64 * 128 * sizeof(uint4);   // 131072 B
    cudaFuncSetAttribute(lstm_kernel, cudaFuncAttributeMaxDynamicSharedMemorySize,
                         (int)smem);

    void* barp = nullptr; cudaGetSymbolAddress(&barp, g_bar);
    void* hptr = nullptr; cudaGetSymbolAddress(&hptr, g_hf);
    cudaMemsetAsync(barp, 0, sizeof(unsigned));
    cudaMemsetAsync(hptr, 0, 2 * H_DIM * sizeof(__half));

    convert_whh<<<(G_DIM * H_DIM / 4 + 255) / 256, 256>>>(W_hh);

    dim3 ggrid(G_DIM / 128, T_STEPS / 128);
    gemm_xg<<<ggrid, 256>>>(input, W_ih, b_ih, b_hh);

    lstm_kernel<<<NB, 256, smem>>>(W_out);

    reduce_out<<<(T_STEPS + 255) / 256, 256>>>(b_out, out);
}

// round 10
// speedup vs baseline: 3.0127x; 1.0969x over previous
#include <cuda_runtime.h>
#include <cuda_fp16.h>
#include <cstdint>
#include <cstddef>

#define T_STEPS 8192
#define F_DIM   1024
#define H_DIM   2048
#define G_DIM   (4 * H_DIM)
#define MAXB    256
#define NB      128            // persistent CTAs: 16 hidden units / 64 gate rows each

// ---------------------------------------------------------------------------
// Static device scratch (no cudaMalloc anywhere)
// ---------------------------------------------------------------------------
__device__ float                    g_XG[(size_t)T_STEPS * G_DIM];   // x-gates, 256 MB
__device__ __half                   g_Whf[(size_t)G_DIM * H_DIM];    // fp16 W_hh, 32 MB
__device__ __half                   g_Xh [(size_t)T_STEPS * F_DIM];  // fp16 input, 16 MB
__device__ __half                   g_Wih[(size_t)G_DIM * F_DIM];    // fp16 W_ih, 16 MB
__device__ __align__(16) __half     g_hf[2][H_DIM];                  // double-buffered h
__device__ float                    g_partial[(size_t)T_STEPS * MAXB];
__device__ unsigned                 g_bar;

// ---------------------------------------------------------------------------
// Helpers
// ---------------------------------------------------------------------------
__device__ __forceinline__ unsigned sptr(const void* p) {
    unsigned a;
    asm("{ .reg .u64 t; cvta.to.shared.u64 t, %1; cvt.u32.u64 %0, t; }"
        : "=r"(a) : "l"(p));
    return a;
}
__device__ __forceinline__ void cp16(unsigned s, const void* g) {
    asm volatile("cp.async.cg.shared.global [%0], [%1], 16;" :: "r"(s), "l"(g));
}
__device__ __forceinline__ __half2 u2h(unsigned x) {
    __half2 h; *reinterpret_cast<unsigned*>(&h) = x; return h;
}
__device__ __forceinline__ void mac4(uint4 w, uint4 h, __half2& acc) {
    acc = __hfma2(u2h(w.x), u2h(h.x), acc);
    acc = __hfma2(u2h(w.y), u2h(h.y), acc);
    acc = __hfma2(u2h(w.z), u2h(h.z), acc);
    acc = __hfma2(u2h(w.w), u2h(h.w), acc);
}
__device__ __forceinline__ float tanh_fast(float x) {
    float y; asm("tanh.approx.f32 %0, %1;" : "=f"(y) : "f"(x)); return y;
}
__device__ __forceinline__ float sig_fast(float x) {
    return 0.5f + 0.5f * tanh_fast(0.5f * x);
}

// ---------------------------------------------------------------------------
// Kernel 1: fp32 -> fp16 conversion (X, W_ih, W_hh)
// ---------------------------------------------------------------------------
__global__ void conv_f2h(const float* __restrict__ S, __half* __restrict__ D, int n4) {
    int i = blockIdx.x * blockDim.x + threadIdx.x;
    if (i >= n4) return;
    float4 v = reinterpret_cast<const float4*>(S)[i];
    __half2* o = reinterpret_cast<__half2*>(D);
    o[i * 2 + 0] = __floats2half2_rn(v.x, v.y);
    o[i * 2 + 1] = __floats2half2_rn(v.z, v.w);
}

// ---------------------------------------------------------------------------
// Kernel 2: XG = X @ W_ih^T + b  via HMMA m16n8k16 (fp16 in, fp32 accum)
// CTA tile 128x128, BK=32, 8 warps (2x4), warp tile 64x32, cp.async dbl-buf.
// ---------------------------------------------------------------------------
__global__ __launch_bounds__(256, 2) void gemm_xg_h(
    const float* __restrict__ bi, const float* __restrict__ bh)
{
    __shared__ __align__(16) __half As[2][128][40];   // stride 40: conflict-free frags
    __shared__ __align__(16) __half Ws[2][128][40];

    const int tid  = threadIdx.x;
    const int lane = tid & 31;
    const int wid  = tid >> 5;
    const int wm   = wid >> 2;          // 0..1
    const int wn   = wid & 3;           // 0..3
    const int bm   = blockIdx.y * 128;  // t
    const int bn   = blockIdx.x * 128;  // g
    const int fg   = lane >> 2;         // fragment row group 0..7
    const int kq   = lane & 3;          // k quad

    float c[4][4][4];
#pragma unroll
    for (int a = 0; a < 4; a++)
#pragma unroll
        for (int b = 0; b < 4; b++)
#pragma unroll
            for (int d = 0; d < 4; d++) c[a][b][d] = 0.f;

    float2 bias2[4];
#pragma unroll
    for (int nb = 0; nb < 4; nb++) {
        int col = bn + wn * 32 + nb * 8 + kq * 2;
        bias2[nb] = make_float2(bi[col] + bh[col], bi[col + 1] + bh[col + 1]);
    }

    const int lrow = tid >> 1, lq = tid & 1;
    const __half* gA = g_Xh  + (size_t)(bm + lrow) * F_DIM + lq * 16;
    const __half* gW = g_Wih + (size_t)(bn + lrow) * F_DIM + lq * 16;

    auto load_buf = [&](int buf, int k0) {
        unsigned da = sptr(&As[buf][lrow][lq * 16]);
        unsigned dw = sptr(&Ws[buf][lrow][lq * 16]);
        cp16(da,      gA + k0);
        cp16(da + 16, gA + k0 + 8);
        cp16(dw,      gW + k0);
        cp16(dw + 16, gW + k0 + 8);
    };

    load_buf(0, 0);
    asm volatile("cp.async.commit_group;" ::: "memory");
    asm volatile("cp.async.wait_group 0;" ::: "memory");
    __syncthreads();

    int buf = 0;
    for (int kt = 0; kt < F_DIM / 32; kt++) {
        if (kt + 1 < F_DIM / 32) {
            load_buf(buf ^ 1, (kt + 1) * 32);
            asm volatile("cp.async.commit_group;" ::: "memory");
        }
#pragma unroll
        for (int ks = 0; ks < 32; ks += 16) {
            unsigned bf[4][2];
#pragma unroll
            for (int nb = 0; nb < 4; nb++) {
                const __half* wp = &Ws[buf][wn * 32 + nb * 8 + fg][ks + kq * 2];
                bf[nb][0] = *reinterpret_cast<const unsigned*>(wp);
                bf[nb][1] = *reinterpret_cast<const unsigned*>(wp + 8);
            }
#pragma unroll
            for (int mb = 0; mb < 4; mb++) {
                const __half* ap = &As[buf][wm * 64 + mb * 16 + fg][ks + kq * 2];
                unsigned a0 = *reinterpret_cast<const unsigned*>(ap);
                unsigned a1 = *reinterpret_cast<const unsigned*>(ap + 8 * 40);
                unsigned a2 = *reinterpret_cast<const unsigned*>(ap + 8);
                unsigned a3 = *reinterpret_cast<const unsigned*>(ap + 8 * 40 + 8);
#pragma unroll
                for (int nb = 0; nb < 4; nb++) {
                    asm volatile(
                        "mma.sync.aligned.m16n8k16.row.col.f32.f16.f16.f32 "
                        "{%0,%1,%2,%3}, {%4,%5,%6,%7}, {%8,%9}, {%0,%1,%2,%3};"
                        : "+f"(c[mb][nb][0]), "+f"(c[mb][nb][1]),
                          "+f"(c[mb][nb][2]), "+f"(c[mb][nb][3])
                        : "r"(a0), "r"(a1), "r"(a2), "r"(a3),
                          "r"(bf[nb][0]), "r"(bf[nb][1]));
                }
            }
        }
        if (kt + 1 < F_DIM / 32)
            asm volatile("cp.async.wait_group 0;" ::: "memory");
        __syncthreads();
        buf ^= 1;
    }

    // epilogue
#pragma unroll
    for (int mb = 0; mb < 4; mb++) {
        int row = bm + wm * 64 + mb * 16 + fg;
#pragma unroll
        for (int nb = 0; nb < 4; nb++) {
            int col = bn + wn * 32 + nb * 8 + kq * 2;
            float2 v0 = make_float2(c[mb][nb][0] + bias2[nb].x,
                                    c[mb][nb][1] + bias2[nb].y);
            float2 v1 = make_float2(c[mb][nb][2] + bias2[nb].x,
                                    c[mb][nb][3] + bias2[nb].y);
            *reinterpret_cast<float2*>(g_XG + (size_t)row * G_DIM + col)       = v0;
            *reinterpret_cast<float2*>(g_XG + (size_t)(row + 8) * G_DIM + col) = v1;
        }
    }
}

// ---------------------------------------------------------------------------
// Kernel 3: persistent HFMA2 LSTM recurrence, row-segment layout.
// 128 CTAs x 256 thr. Thread (w,l): row = 8w + (l>>2), K-segment = l&3 (512 k).
// Segment: first 256 k in registers, last 256 k in SMEM (lane-transposed).
// Quad reduction: 2 SHFLs. Sigmoid via tanh.approx.
// ---------------------------------------------------------------------------
__global__ __launch_bounds__(256, 1) void lstm_kernel(
    const float* __restrict__ Wout)
{
    extern __shared__ uint4 wsmT[];       // 32 x 256 uint4 = 128 KB, lane-transposed
    __shared__ uint4  h_sm4[4 * 65];      // h segments, stride 65 (conflict-free)
    __shared__ float  gates_sm[64];
    __shared__ float  xg_sm[2][64];

    const int tid  = threadIdx.x;
    const int lane = tid & 31;
    const int wid  = tid >> 5;
    const int b    = blockIdx.x;
    const int base = b * 16;

    const int row = wid * 8 + (lane >> 2);        // 0..63 local gate row
    const int seg = lane & 3;                     // K segment

    auto growm = [&](int m) -> size_t {
        return (size_t)(m >> 4) * H_DIM + base + (m & 15);
    };

    const uint4* wp = reinterpret_cast<const uint4*>(
        g_Whf + growm(row) * H_DIM + seg * 512);

    // register weights: k [seg*512, seg*512+256)
    uint4 wreg[32];
#pragma unroll
    for (int i = 0; i < 32; i++) wreg[i] = __ldg(wp + i);
    // SMEM weights (transposed): k [seg*512+256, seg*512+512)
    for (int i = 0; i < 32; i++) wsmT[i * 256 + tid] = __ldg(wp + 32 + i);

    float creg = 0.f;
    const float wout = (wid == 0 && lane < 16) ? Wout[base + lane] : 0.f;

    if (wid < 2) {
        int m = wid * 32 + lane;
        xg_sm[0][m] = __ldg(g_XG + growm(m));
    }
    __syncthreads();

    for (int t = 0; t < T_STEPS; t++) {
        // ---- stage h (fp16) into padded SMEM segments ----
        {
            const uint4* hg = reinterpret_cast<const uint4*>(g_hf[t & 1]);
            uint4 v = __ldcg(hg + tid);
            h_sm4[(tid >> 6) * 65 + (tid & 63)] = v;
        }
        __syncthreads();

        // ---- per-thread dot over its 512-k segment ----
        const uint4* hA = &h_sm4[seg * 65];
        const uint4* hB = &h_sm4[seg * 65 + 32];
        float dot = 0.f;
        __half2 acc = __half2half2(__ushort_as_half(0));
#pragma unroll
        for (int i = 0; i < 32; i += 2) {
            mac4(wreg[i],     hA[i],     acc);
            mac4(wreg[i + 1], hA[i + 1], acc);
            float2 f = __half22float2(acc);
            dot += f.x + f.y;
            acc = __half2half2(__ushort_as_half(0));
        }
#pragma unroll
        for (int i = 0; i < 32; i += 2) {
            mac4(wsmT[i * 256 + tid],       hB[i],     acc);
            mac4(wsmT[(i + 1) * 256 + tid], hB[i + 1], acc);
            float2 f = __half22float2(acc);
            dot += f.x + f.y;
            acc = __half2half2(__ushort_as_half(0));
        }

        // ---- quad reduction (segments are lanes l^1, l^2) ----
        dot += __shfl_xor_sync(0xffffffffu, dot, 1);
        dot += __shfl_xor_sync(0xffffffffu, dot, 2);
        if (seg == 0) gates_sm[row] = dot;
        __syncthreads();

        // ---- activations (warp 0, lanes 0-15) + h publish ----
        float hn = 0.f;
        if (wid == 0) {
            if (lane < 16) {
                float iv = gates_sm[lane]      + xg_sm[t & 1][lane];
                float fv = gates_sm[16 + lane] + xg_sm[t & 1][16 + lane];
                float gv = gates_sm[32 + lane] + xg_sm[t & 1][32 + lane];
                float ov = gates_sm[48 + lane] + xg_sm[t & 1][48 + lane];
                float cn = sig_fast(fv) * creg + sig_fast(iv) * tanh_fast(gv);
                hn = sig_fast(ov) * tanh_fast(cn);
                creg = cn;
                g_hf[(t + 1) & 1][base + lane] = __float2half_rn(hn);
            }
            __syncwarp();
            // barrier arrival: release orders this warp's h stores
            if (t < T_STEPS - 1 && lane == 0) {
                asm volatile("red.release.gpu.global.add.u32 [%0], 1;"
                             :: "l"(&g_bar) : "memory");
            }
            // shadow: output partial
            float pv = hn * wout;
#pragma unroll
            for (int o = 16; o; o >>= 1) pv += __shfl_xor_sync(0xffffffffu, pv, o);
            if (lane == 0) g_partial[(size_t)t * MAXB + b] = pv;
        }

        // shadow: xg prefetch into the other buffer (warps 1,2)
        if ((wid == 1 || wid == 2) && t + 1 < T_STEPS) {
            int m = (wid - 1) * 32 + lane;
            xg_sm[(t + 1) & 1][m] = __ldg(g_XG + (size_t)(t + 1) * G_DIM + growm(m));
        }

        // ---- barrier wait ----
        if (t < T_STEPS - 1) {
            if (tid == 0) {
                const unsigned target = (unsigned)NB * (unsigned)(t + 1);
                unsigned v;
                do {
                    asm volatile("ld.acquire.gpu.global.u32 %0, [%1];"
                                 : "=r"(v) : "l"(&g_bar) : "memory");
                } while (v < target);
            }
            __syncthreads();
        }
    }
}

// ---------------------------------------------------------------------------
// Kernel 4: out[t] = b_out + sum_b partial[t][b]  (fixed order, deterministic)
// ---------------------------------------------------------------------------
__global__ void reduce_out(const float* __restrict__ bo, float* __restrict__ out) {
    int t = blockIdx.x * blockDim.x + threadIdx.x;
    if (t >= T_STEPS) return;
    float s = bo[0];
    const float* p = g_partial + (size_t)t * MAXB;
    for (int b = 0; b < NB; b++) s += p[b];
    out[t] = s;
}

// ---------------------------------------------------------------------------
// Host launcher (graph-capturable: kernels + async memsets only)
// ---------------------------------------------------------------------------
extern "C" void kernel_launch(void* const* d_in, const int* in_sizes, int n_in,
                              void* d_out, int out_size)
{
    const float* input = (const float*)d_in[0];   // [T, 1, F]
    const float* W_ih  = (const float*)d_in[1];   // [4H, F]
    const float* W_hh  = (const float*)d_in[2];   // [4H, H]
    const float* b_ih  = (const float*)d_in[3];
    const float* b_hh  = (const float*)d_in[4];
    const float* W_out = (const float*)d_in[5];   // [1, H]
    const float* b_out = (const float*)d_in[6];
    float* out = (float*)d_out;                   // [T, 1, 1]

    const size_t smem = (size_t)32 * 256 * sizeof(uint4);   // 131072 B
    cudaFuncSetAttribute(lstm_kernel, cudaFuncAttributeMaxDynamicSharedMemorySize,
                         (int)smem);

    void* barp = nullptr; cudaGetSymbolAddress(&barp, g_bar);
    void* hptr = nullptr; cudaGetSymbolAddress(&hptr, g_hf);
    cudaMemsetAsync(barp, 0, sizeof(unsigned));
    cudaMemsetAsync(hptr, 0, 2 * H_DIM * sizeof(__half));

    __half* xh = nullptr;  cudaGetSymbolAddress((void**)&xh,  g_Xh);
    __half* wih = nullptr; cudaGetSymbolAddress((void**)&wih, g_Wih);
    __half* whf = nullptr; cudaGetSymbolAddress((void**)&whf, g_Whf);

    conv_f2h<<<(T_STEPS * F_DIM / 4 + 255) / 256, 256>>>(input, xh,
                                                         T_STEPS * F_DIM / 4);
    conv_f2h<<<(G_DIM * F_DIM / 4 + 255) / 256, 256>>>(W_ih, wih,
                                                       G_DIM * F_DIM / 4);
    conv_f2h<<<(G_DIM * H_DIM / 4 + 255) / 256, 256>>>(W_hh, whf,
                                                       G_DIM * H_DIM / 4);

    dim3 ggrid(G_DIM / 128, T_STEPS / 128);
    gemm_xg_h<<<ggrid, 256>>>(b_ih, b_hh);

    lstm_kernel<<<NB, 256, smem>>>(W_out);

    reduce_out<<<(T_STEPS + 255) / 256, 256>>>(b_out, out);
}